// round 6
// baseline (speedup 1.0000x reference)
#include <cuda_runtime.h>
#include <math.h>
#include <stdint.h>

#define BATCH 2
#define SEQ   2048
#define EMB   1024
#define NH    16
#define HD    64
#define NTOK  (BATCH*SEQ)   // 4096

// Scratch (allocation-free).
static __device__ float g_qkv[(size_t)NTOK * 3 * EMB];      // QKV projections
static __device__ float g_attn[(size_t)NTOK * EMB];         // attention output
static __device__ float g_w_inT[(size_t)3 * EMB * EMB];     // w_in^T  [3E][E]
static __device__ float g_w_outT[(size_t)EMB * EMB];        // w_out^T [E][E]

// ===========================================================================
// PTX helpers (sm_80-baseline instructions only: mma.sync tf32 + ldmatrix)
// ===========================================================================
__device__ __forceinline__ uint32_t smem_u32(const void* p) {
    uint32_t a;
    asm("{ .reg .u64 t; cvta.to.shared.u64 t, %1; cvt.u32.u64 %0, t; }"
        : "=r"(a) : "l"(p));
    return a;
}

__device__ __forceinline__ uint32_t f2tf32(float x) {
    uint32_t u;
    asm("cvt.rna.tf32.f32 %0, %1;" : "=r"(u) : "f"(x));
    return u;
}

__device__ __forceinline__ void ldsm_x4(uint32_t* r, uint32_t addr) {
    asm volatile("ldmatrix.sync.aligned.m8n8.x4.shared.b16 {%0,%1,%2,%3}, [%4];"
                 : "=r"(r[0]), "=r"(r[1]), "=r"(r[2]), "=r"(r[3]) : "r"(addr));
}
__device__ __forceinline__ void ldsm_x2(uint32_t* r, uint32_t addr) {
    asm volatile("ldmatrix.sync.aligned.m8n8.x2.shared.b16 {%0,%1}, [%2];"
                 : "=r"(r[0]), "=r"(r[1]) : "r"(addr));
}

__device__ __forceinline__ void mma_tf32(float* c, const uint32_t* a, const uint32_t* b) {
    asm volatile(
        "mma.sync.aligned.m16n8k8.row.col.f32.tf32.tf32.f32 "
        "{%0,%1,%2,%3}, {%4,%5,%6,%7}, {%8,%9}, {%0,%1,%2,%3};"
        : "+f"(c[0]), "+f"(c[1]), "+f"(c[2]), "+f"(c[3])
        : "r"(a[0]), "r"(a[1]), "r"(a[2]), "r"(a[3]), "r"(b[0]), "r"(b[1]));
}

// ===========================================================================
// Tiled transpose: out[C][R] = in[R][C]
// ===========================================================================
__global__ void transpose_kernel(const float* __restrict__ in, float* __restrict__ out,
                                 int R, int C)
{
    __shared__ float t[32][33];
    int c0 = blockIdx.x * 32, r0 = blockIdx.y * 32;
    int x = threadIdx.x, y = threadIdx.y;   // block (32,8)
#pragma unroll
    for (int i = 0; i < 32; i += 8)
        t[y + i][x] = in[(size_t)(r0 + y + i) * C + c0 + x];
    __syncthreads();
#pragma unroll
    for (int i = 0; i < 32; i += 8)
        out[(size_t)(c0 + y + i) * R + r0 + x] = t[x][y + i];
}

// ===========================================================================
// TF32 mma.sync GEMM + bias: C[M,N] = A[M,K] @ Bt[N,K]^T + bias[N]
// CTA 128x128x32, 256 threads, 8 warps (2x4), warp tile 64x32 (4x4 atoms of
// m16n8k8). Tiles stored with 128B rows + Swizzle<3,4,3>; ldmatrix fragments.
// ===========================================================================
__global__ __launch_bounds__(256, 2)
void gemm_mma(const float* __restrict__ A, const float* __restrict__ Bt,
              const float* __restrict__ bias, float* __restrict__ C,
              int M, int N, int K)
{
    __shared__ float As[128 * 32];   // [m][k], swizzled, 16KB
    __shared__ float Bs[128 * 32];   // [n][k], swizzled, 16KB
    const uint32_t as_base = smem_u32(As);
    const uint32_t bs_base = smem_u32(Bs);

    const int tid  = threadIdx.x;
    const int wid  = tid >> 5, lane = tid & 31;
    const int wm   = wid >> 2;      // 0..1  (64 rows each)
    const int wn   = wid & 3;       // 0..3  (32 cols each)
    const int mBase = blockIdx.y * 128;
    const int nBase = blockIdx.x * 128;

    // ldmatrix per-lane addressing components.
    const int a_tile = lane >> 3, a_r = lane & 7;          // x4: 4 tiles
    const int b_tile = (lane >> 3) & 1, b_r = lane & 7;    // x2: 2 tiles

    float c[4][4][4];
#pragma unroll
    for (int mi = 0; mi < 4; mi++)
#pragma unroll
        for (int ni = 0; ni < 4; ni++)
#pragma unroll
            for (int j = 0; j < 4; j++) c[mi][ni][j] = 0.f;

    const float* Ag = A  + (size_t)mBase * K;
    const float* Bg = Bt + (size_t)nBase * K;

    for (int k0 = 0; k0 < K; k0 += 32) {
        // Fill tiles: 128 rows x 8 float4-chunks each; cvt.rna to tf32.
#pragma unroll
        for (int it = 0; it < 4; it++) {
            int f   = tid + it * 256;
            int row = f >> 3, kq = f & 7;
            uint32_t off = row * 128 + kq * 16;
            off ^= (off >> 3) & 0x70;
            float4 va = *(const float4*)(Ag + (size_t)row * K + k0 + kq * 4);
            uint4 ta = make_uint4(f2tf32(va.x), f2tf32(va.y), f2tf32(va.z), f2tf32(va.w));
            *(uint4*)((char*)As + off) = ta;
            float4 vb = *(const float4*)(Bg + (size_t)row * K + k0 + kq * 4);
            uint4 tb = make_uint4(f2tf32(vb.x), f2tf32(vb.y), f2tf32(vb.z), f2tf32(vb.w));
            *(uint4*)((char*)Bs + off) = tb;
        }
        __syncthreads();

#pragma unroll
        for (int kk = 0; kk < 32; kk += 8) {
            uint32_t af[4][4], bf[4][2];
#pragma unroll
            for (int mi = 0; mi < 4; mi++) {
                int m = wm * 64 + mi * 16 + a_r + (a_tile & 1) * 8;
                int k = kk + (a_tile >> 1) * 4;
                uint32_t off = m * 128 + k * 4;
                off ^= (off >> 3) & 0x70;
                ldsm_x4(af[mi], as_base + off);
            }
#pragma unroll
            for (int ni = 0; ni < 4; ni++) {
                int n = wn * 32 + ni * 8 + b_r;
                int k = kk + b_tile * 4;
                uint32_t off = n * 128 + k * 4;
                off ^= (off >> 3) & 0x70;
                ldsm_x2(bf[ni], bs_base + off);
            }
#pragma unroll
            for (int mi = 0; mi < 4; mi++)
#pragma unroll
                for (int ni = 0; ni < 4; ni++)
                    mma_tf32(c[mi][ni], af[mi], bf[ni]);
        }
        __syncthreads();
    }

    // Epilogue: c0/c1 at (row, 2q), c2/c3 at (row+8, 2q).
    const int r = lane >> 2, q = lane & 3;
#pragma unroll
    for (int mi = 0; mi < 4; mi++) {
        int m0 = mBase + wm * 64 + mi * 16 + r;
#pragma unroll
        for (int ni = 0; ni < 4; ni++) {
            int n0 = nBase + wn * 32 + ni * 8 + q * 2;
            float2 bv = *(const float2*)(bias + n0);
            float2 o0, o1;
            o0.x = c[mi][ni][0] + bv.x; o0.y = c[mi][ni][1] + bv.y;
            o1.x = c[mi][ni][2] + bv.x; o1.y = c[mi][ni][3] + bv.y;
            *(float2*)(C + (size_t)m0 * N + n0)       = o0;
            *(float2*)(C + (size_t)(m0 + 8) * N + n0) = o1;
        }
    }
}

// ===========================================================================
// Flash attention, fp32 (unchanged from passing baseline).
// ===========================================================================
#define ATTN_SMEM_FLOATS (64*132 + 64*68 + 64*64 + 64*132 + 3*128)
#define ATTN_SMEM_BYTES  (ATTN_SMEM_FLOATS * 4)

__global__ __launch_bounds__(128, 2)
void mha_attn_kernel(const float* __restrict__ qkv, float* __restrict__ out)
{
    extern __shared__ float smbuf[];
    float* Qs   = smbuf;
    float* Ks   = Qs + 64 * 132;
    float* Vs   = Ks + 64 * 68;
    float* Ss   = Vs + 64 * 64;
    float* st_m = Ss + 64 * 132;
    float* st_l = st_m + 128;
    float* st_a = st_l + 128;

    const int tid = threadIdx.x;
    const int ty  = tid & 15;
    const int tx  = tid >> 4;
    const int h   = blockIdx.y & (NH - 1);
    const int b   = blockIdx.y >> 4;
    const int q0  = blockIdx.x * 128;
    const size_t rs = 3 * EMB;

    const float* Qg = qkv + ((size_t)b * SEQ + q0) * rs + h * HD;
    const float* Kg = qkv + (size_t)b * SEQ * rs + EMB + h * HD;

#pragma unroll
    for (int it = 0; it < 16; it++) {
        int f  = tid + it * 128;
        int m  = f >> 4;
        int d4 = f & 15;
        float4 v = *(const float4*)(Qg + (size_t)m * rs + d4 * 4);
        Qs[(d4 * 4 + 0) * 132 + m] = v.x * 0.125f;
        Qs[(d4 * 4 + 1) * 132 + m] = v.y * 0.125f;
        Qs[(d4 * 4 + 2) * 132 + m] = v.z * 0.125f;
        Qs[(d4 * 4 + 3) * 132 + m] = v.w * 0.125f;
    }
    st_m[tid] = -1e30f;
    st_l[tid] = 0.f;

    float o[8][8];
#pragma unroll
    for (int i = 0; i < 8; i++)
#pragma unroll
        for (int j = 0; j < 8; j++) o[i][j] = 0.f;

    __syncthreads();

    for (int kt = 0; kt < SEQ; kt += 64) {
#pragma unroll
        for (int it = 0; it < 8; it++) {
            int f  = tid + it * 128;
            int n  = f >> 4;
            int d4 = f & 15;
            const float* kp = Kg + (size_t)(kt + n) * rs + d4 * 4;
            float4 kv = *(const float4*)kp;
            float4 vv = *(const float4*)(kp + EMB);
            Ks[(d4 * 4 + 0) * 68 + n] = kv.x;
            Ks[(d4 * 4 + 1) * 68 + n] = kv.y;
            Ks[(d4 * 4 + 2) * 68 + n] = kv.z;
            Ks[(d4 * 4 + 3) * 68 + n] = kv.w;
            *(float4*)&Vs[n * 64 + d4 * 4] = vv;
        }
        __syncthreads();

        float s[8][8];
#pragma unroll
        for (int i = 0; i < 8; i++)
#pragma unroll
            for (int j = 0; j < 8; j++) s[i][j] = 0.f;

#pragma unroll 8
        for (int d = 0; d < 64; d++) {
            float a[8], bb[8];
            *(float4*)&a[0]  = *(const float4*)&Qs[d * 132 + ty * 8];
            *(float4*)&a[4]  = *(const float4*)&Qs[d * 132 + ty * 8 + 4];
            *(float4*)&bb[0] = *(const float4*)&Ks[d * 68 + tx * 8];
            *(float4*)&bb[4] = *(const float4*)&Ks[d * 68 + tx * 8 + 4];
#pragma unroll
            for (int i = 0; i < 8; i++)
#pragma unroll
                for (int j = 0; j < 8; j++)
                    s[i][j] = fmaf(a[i], bb[j], s[i][j]);
        }

#pragma unroll
        for (int j = 0; j < 8; j++) {
            int n = tx * 8 + j;
            float4 v0 = make_float4(s[0][j], s[1][j], s[2][j], s[3][j]);
            float4 v1 = make_float4(s[4][j], s[5][j], s[6][j], s[7][j]);
            *(float4*)&Ss[n * 132 + ty * 8]     = v0;
            *(float4*)&Ss[n * 132 + ty * 8 + 4] = v1;
        }
        __syncthreads();

        {
            float mo = st_m[tid];
            float mx = mo;
#pragma unroll 8
            for (int n = 0; n < 64; n++)
                mx = fmaxf(mx, Ss[n * 132 + tid]);
            float alpha = __expf(mo - mx);
            float l = st_l[tid] * alpha;
#pragma unroll 8
            for (int n = 0; n < 64; n++) {
                float p = __expf(Ss[n * 132 + tid] - mx);
                Ss[n * 132 + tid] = p;
                l += p;
            }
            st_m[tid] = mx;
            st_l[tid] = l;
            st_a[tid] = alpha;
        }
        __syncthreads();

        float al[8];
#pragma unroll
        for (int i = 0; i < 8; i++) al[i] = st_a[ty * 8 + i];
#pragma unroll
        for (int i = 0; i < 8; i++)
#pragma unroll
            for (int j = 0; j < 8; j++) o[i][j] *= al[i];

#pragma unroll 8
        for (int kv = 0; kv < 64; kv++) {
            float a[8], bb[8];
            *(float4*)&a[0]  = *(const float4*)&Ss[kv * 132 + ty * 8];
            *(float4*)&a[4]  = *(const float4*)&Ss[kv * 132 + ty * 8 + 4];
            *(float4*)&bb[0] = *(const float4*)&Vs[kv * 64 + tx * 8];
            *(float4*)&bb[4] = *(const float4*)&Vs[kv * 64 + tx * 8 + 4];
#pragma unroll
            for (int i = 0; i < 8; i++)
#pragma unroll
                for (int j = 0; j < 8; j++)
                    o[i][j] = fmaf(a[i], bb[j], o[i][j]);
        }
        __syncthreads();
    }

    float inv[8];
#pragma unroll
    for (int i = 0; i < 8; i++) inv[i] = 1.0f / st_l[ty * 8 + i];

    const size_t orow = (size_t)b * SEQ + q0;
#pragma unroll
    for (int i = 0; i < 8; i++) {
        int m = ty * 8 + i;
        float4 v0, v1;
        v0.x = o[i][0] * inv[i]; v0.y = o[i][1] * inv[i];
        v0.z = o[i][2] * inv[i]; v0.w = o[i][3] * inv[i];
        v1.x = o[i][4] * inv[i]; v1.y = o[i][5] * inv[i];
        v1.z = o[i][6] * inv[i]; v1.w = o[i][7] * inv[i];
        float* dst = out + (orow + m) * EMB + h * HD + tx * 8;
        *(float4*)dst       = v0;
        *(float4*)(dst + 4) = v1;
    }
}

// ===========================================================================
extern "C" void kernel_launch(void* const* d_in, const int* in_sizes, int n_in,
                              void* d_out, int out_size)
{
    const float* x     = (const float*)d_in[0];
    const float* w_in  = (const float*)d_in[1];
    const float* b_in  = (const float*)d_in[2];
    const float* w_out = (const float*)d_in[3];
    const float* b_out = (const float*)d_in[4];
    float* out = (float*)d_out;

    static float* qkv_buf  = nullptr;
    static float* attn_buf = nullptr;
    static float* w_inT    = nullptr;
    static float* w_outT   = nullptr;
    static bool   init     = false;
    if (!init) {
        cudaGetSymbolAddress((void**)&qkv_buf,  g_qkv);
        cudaGetSymbolAddress((void**)&attn_buf, g_attn);
        cudaGetSymbolAddress((void**)&w_inT,    g_w_inT);
        cudaGetSymbolAddress((void**)&w_outT,   g_w_outT);
        cudaFuncSetAttribute(mha_attn_kernel,
                             cudaFuncAttributeMaxDynamicSharedMemorySize,
                             ATTN_SMEM_BYTES);
        init = true;
    }

    // 0) Transpose weights to K-major (Bt layout) for the mma GEMMs.
    transpose_kernel<<<dim3(3 * EMB / 32, EMB / 32), dim3(32, 8)>>>(w_in,  w_inT,  EMB, 3 * EMB);
    transpose_kernel<<<dim3(EMB / 32,     EMB / 32), dim3(32, 8)>>>(w_out, w_outT, EMB, EMB);

    // 1) QKV projection: [4096,1024] @ [1024,3072] + b_in   (tf32 mma)
    gemm_mma<<<dim3(3 * EMB / 128, NTOK / 128), 256>>>(
        x, w_inT, b_in, qkv_buf, NTOK, 3 * EMB, EMB);

    // 2) Attention per (batch, head), 128-query tiles (fp32)
    mha_attn_kernel<<<dim3(SEQ / 128, BATCH * NH), 128, ATTN_SMEM_BYTES>>>(
        qkv_buf, attn_buf);

    // 3) Output projection: [4096,1024] @ [1024,1024] + b_out  (tf32 mma)
    gemm_mma<<<dim3(EMB / 128, NTOK / 128), 256>>>(
        attn_buf, w_outT, b_out, out, NTOK, EMB, EMB);
}

// round 12
// speedup vs baseline: 3.8822x; 3.8822x over previous
#include <cuda_runtime.h>
#include <math.h>
#include <stdint.h>

#define BATCH 2
#define SEQ   2048
#define EMB   1024
#define NH    16
#define HD    64
#define NTOK  (BATCH*SEQ)   // 4096

// Scratch (allocation-free).
static __device__ float g_x[(size_t)NTOK * EMB];            // tf32-rounded x
static __device__ float g_qkv[(size_t)NTOK * 3 * EMB];      // QKV projections
static __device__ float g_attn[(size_t)NTOK * EMB];         // attention output (tf32 bits)
static __device__ float g_w_inT[(size_t)3 * EMB * EMB];     // w_in^T  (tf32 bits)
static __device__ float g_w_outT[(size_t)EMB * EMB];        // w_out^T (tf32 bits)

// ===========================================================================
// PTX helpers (sm_80-baseline: mma.sync tf32, ldmatrix, cp.async)
// ===========================================================================
__device__ __forceinline__ uint32_t smem_u32(const void* p) {
    uint32_t a;
    asm("{ .reg .u64 t; cvta.to.shared.u64 t, %1; cvt.u32.u64 %0, t; }"
        : "=r"(a) : "l"(p));
    return a;
}
__device__ __forceinline__ uint32_t f2tf32(float x) {
    uint32_t u;
    asm("cvt.rna.tf32.f32 %0, %1;" : "=r"(u) : "f"(x));
    return u;
}
__device__ __forceinline__ void ldsm_x4(uint32_t* r, uint32_t addr) {
    asm volatile("ldmatrix.sync.aligned.m8n8.x4.shared.b16 {%0,%1,%2,%3}, [%4];"
                 : "=r"(r[0]), "=r"(r[1]), "=r"(r[2]), "=r"(r[3]) : "r"(addr));
}
__device__ __forceinline__ void ldsm_x2(uint32_t* r, uint32_t addr) {
    asm volatile("ldmatrix.sync.aligned.m8n8.x2.shared.b16 {%0,%1}, [%2];"
                 : "=r"(r[0]), "=r"(r[1]) : "r"(addr));
}
__device__ __forceinline__ void mma_tf32(float* c, const uint32_t* a, const uint32_t* b) {
    asm volatile(
        "mma.sync.aligned.m16n8k8.row.col.f32.tf32.tf32.f32 "
        "{%0,%1,%2,%3}, {%4,%5,%6,%7}, {%8,%9}, {%0,%1,%2,%3};"
        : "+f"(c[0]), "+f"(c[1]), "+f"(c[2]), "+f"(c[3])
        : "r"(a[0]), "r"(a[1]), "r"(a[2]), "r"(a[3]), "r"(b[0]), "r"(b[1]));
}
__device__ __forceinline__ void cp_async16(uint32_t dst, const void* src) {
    asm volatile("cp.async.cg.shared.global [%0], [%1], 16;" :: "r"(dst), "l"(src));
}
#define CP_COMMIT() asm volatile("cp.async.commit_group;" ::: "memory")
#define CP_WAIT(n)  asm volatile("cp.async.wait_group %0;" :: "n"(n) : "memory")

// ===========================================================================
// Pre-passes: tf32 rounding + transposed-rounded weights
// ===========================================================================
__global__ void round_tf32_kernel(const float* __restrict__ in, float* __restrict__ out)
{
    int i = (blockIdx.x * blockDim.x + threadIdx.x) * 4;
    float4 v = *(const float4*)(in + i);
    uint4 t = make_uint4(f2tf32(v.x), f2tf32(v.y), f2tf32(v.z), f2tf32(v.w));
    *(uint4*)(out + i) = t;
}

__global__ void transpose_round_kernel(const float* __restrict__ in, float* __restrict__ out,
                                       int R, int C)
{
    __shared__ float t[32][33];
    int c0 = blockIdx.x * 32, r0 = blockIdx.y * 32;
    int x = threadIdx.x, y = threadIdx.y;   // block (32,8)
#pragma unroll
    for (int i = 0; i < 32; i += 8)
        t[y + i][x] = in[(size_t)(r0 + y + i) * C + c0 + x];
    __syncthreads();
#pragma unroll
    for (int i = 0; i < 32; i += 8)
        out[(size_t)(c0 + y + i) * R + r0 + x] = __uint_as_float(f2tf32(t[x][y + i]));
}

// ===========================================================================
// TF32 mma GEMM + bias, cp.async double-buffered.
// C[M,N] = A[M,K] @ Bt[N,K]^T + bias[N]. A, Bt pre-rounded to tf32 bits.
// CTA 128x128x32, 256 threads, 8 warps (2x4), warp tile 64x32.
// Dynamic smem: stage s at s*32768 (A 16KB | B 16KB), 2 stages = 64KB.
// ===========================================================================
__global__ __launch_bounds__(256, 2)
void gemm_mma(const float* __restrict__ A, const float* __restrict__ Bt,
              const float* __restrict__ bias, float* __restrict__ C,
              int M, int N, int K)
{
    extern __shared__ char gsm[];
    const uint32_t sbase = smem_u32(gsm);

    const int tid  = threadIdx.x;
    const int wid  = tid >> 5, lane = tid & 31;
    const int wm   = wid >> 2;      // 0..1
    const int wn   = wid & 3;       // 0..3
    const int mBase = blockIdx.y * 128;
    const int nBase = blockIdx.x * 128;

    const int a_tile = lane >> 3, a_r = lane & 7;
    const int b_tile = (lane >> 3) & 1, b_r = lane & 7;

    const float* Ag = A  + (size_t)mBase * K;
    const float* Bg = Bt + (size_t)nBase * K;

    const int ld_row = tid >> 3, ld_kq = tid & 7;   // 32 rows per pass, 4 passes

    // Issue one stage's loads (A and B tiles, 128x32 each).
    auto issue = [&](int stage, int k0) {
#pragma unroll
        for (int it = 0; it < 4; it++) {
            int row = ld_row + it * 32;
            uint32_t off = row * 128 + ld_kq * 16;
            off ^= (off >> 3) & 0x70;
            cp_async16(sbase + stage * 32768 + off,
                       Ag + (size_t)row * K + k0 + ld_kq * 4);
            cp_async16(sbase + stage * 32768 + 16384 + off,
                       Bg + (size_t)row * K + k0 + ld_kq * 4);
        }
        CP_COMMIT();
    };

    float c[4][4][4];
#pragma unroll
    for (int mi = 0; mi < 4; mi++)
#pragma unroll
        for (int ni = 0; ni < 4; ni++)
#pragma unroll
            for (int j = 0; j < 4; j++) c[mi][ni][j] = 0.f;

    const int niter = K / 32;
    issue(0, 0);

    for (int i = 0; i < niter; i++) {
        if (i + 1 < niter) issue((i + 1) & 1, (i + 1) * 32);
        if (i + 1 < niter) { CP_WAIT(1); } else { CP_WAIT(0); }
        __syncthreads();

        const uint32_t as_b = sbase + (i & 1) * 32768;
        const uint32_t bs_b = as_b + 16384;

#pragma unroll
        for (int kk = 0; kk < 32; kk += 8) {
            uint32_t af[4][4], bf[4][2];
#pragma unroll
            for (int mi = 0; mi < 4; mi++) {
                int m = wm * 64 + mi * 16 + a_r + (a_tile & 1) * 8;
                int k = kk + (a_tile >> 1) * 4;
                uint32_t off = m * 128 + k * 4;
                off ^= (off >> 3) & 0x70;
                ldsm_x4(af[mi], as_b + off);
            }
#pragma unroll
            for (int ni = 0; ni < 4; ni++) {
                int n = wn * 32 + ni * 8 + b_r;
                int k = kk + b_tile * 4;
                uint32_t off = n * 128 + k * 4;
                off ^= (off >> 3) & 0x70;
                ldsm_x2(bf[ni], bs_b + off);
            }
#pragma unroll
            for (int mi = 0; mi < 4; mi++)
#pragma unroll
                for (int ni = 0; ni < 4; ni++)
                    mma_tf32(c[mi][ni], af[mi], bf[ni]);
        }
        __syncthreads();
    }

    const int r = lane >> 2, q = lane & 3;
#pragma unroll
    for (int mi = 0; mi < 4; mi++) {
        int m0 = mBase + wm * 64 + mi * 16 + r;
#pragma unroll
        for (int ni = 0; ni < 4; ni++) {
            int n0 = nBase + wn * 32 + ni * 8 + q * 2;
            float2 bv = *(const float2*)(bias + n0);
            float2 o0, o1;
            o0.x = c[mi][ni][0] + bv.x; o0.y = c[mi][ni][1] + bv.y;
            o1.x = c[mi][ni][2] + bv.x; o1.y = c[mi][ni][3] + bv.y;
            *(float2*)(C + (size_t)m0 * N + n0)       = o0;
            *(float2*)(C + (size_t)(m0 + 8) * N + n0) = o1;
        }
    }
}

// ===========================================================================
// Flash attention, TF32 mma.sync. One CTA = 128 queries x (batch, head).
// 4 warps; warp w owns query rows w*32..w*32+31 (2 m16 tiles).
// KV tiles of 64. All smem tiles use stride-68 rows (272B = 17*16B):
// ldmatrix row step = 4 banks -> conflict-free.
// smem: Qs 128x68 | Ks 64x68 | Vt 64x68 | Ps 128x68  = 104448 B
//
// B-fragment gather via one ldsm_x4 over a 16(n) x 8(k) region:
//   tmp[0] = n[0:8),k[0:4)   tmp[1] = n[0:8),k[4:8)
//   tmp[2] = n[8:16),k[0:4)  tmp[3] = n[8:16),k[4:8)
// -> bf[2*np]   = {tmp[0], tmp[1]}   (n-subtile 0: b0=k lo, b1=k hi)
//    bf[2*np+1] = {tmp[2], tmp[3]}   (n-subtile 1)
// ===========================================================================
#define AST 68
#define ATTN_SMEM_BYTES ((128*AST + 64*AST + 64*AST + 128*AST) * 4)

__global__ __launch_bounds__(128, 2)
void mha_mma_kernel(const float* __restrict__ qkv, float* __restrict__ out)
{
    extern __shared__ float smf[];
    float* Qs = smf;                 // [m][d]
    float* Ks = Qs + 128 * AST;      // [kv][d]
    float* Vt = Ks + 64 * AST;       // [d][kv]
    float* Ps = Vt + 64 * AST;       // [m][kv]
    const uint32_t qs_b = smem_u32(Qs), ks_b = smem_u32(Ks);
    const uint32_t vt_b = smem_u32(Vt), ps_b = smem_u32(Ps);

    const int tid  = threadIdx.x;
    const int warp = tid >> 5, lane = tid & 31;
    const int r = lane >> 2, q = lane & 3;
    const int a_tile = lane >> 3, a_r = lane & 7;

    const int h  = blockIdx.y & (NH - 1);
    const int b  = blockIdx.y >> 4;
    const int q0 = blockIdx.x * 128;
    const size_t rs = 3 * EMB;

    const float* Qg = qkv + ((size_t)b * SEQ + q0) * rs + h * HD;
    const float* Kg = qkv + (size_t)b * SEQ * rs + EMB + h * HD;
    const float* Vg = qkv + (size_t)b * SEQ * rs + 2 * EMB + h * HD;

    // Load Q tile (128x64), scale by 1/8, round to tf32.
#pragma unroll
    for (int it = 0; it < 16; it++) {
        int f = tid + it * 128;
        int m = f >> 4, c4 = f & 15;
        float4 v = *(const float4*)(Qg + (size_t)m * rs + c4 * 4);
        uint4 t = make_uint4(f2tf32(v.x * 0.125f), f2tf32(v.y * 0.125f),
                             f2tf32(v.z * 0.125f), f2tf32(v.w * 0.125f));
        *(uint4*)(Qs + m * AST + c4 * 4) = t;
    }

    float o[2][8][4];
#pragma unroll
    for (int mi = 0; mi < 2; mi++)
#pragma unroll
        for (int ni = 0; ni < 8; ni++)
#pragma unroll
            for (int j = 0; j < 4; j++) o[mi][ni][j] = 0.f;
    float m_st[2][2] = {{-1e30f, -1e30f}, {-1e30f, -1e30f}};
    float l_st[2][2] = {{0.f, 0.f}, {0.f, 0.f}};

    __syncthreads();

    for (int kt = 0; kt < SEQ; kt += 64) {
        // K tile: direct [kv][d] copy, rounded.
#pragma unroll
        for (int it = 0; it < 8; it++) {
            int f = tid + it * 128;
            int n = f >> 4, c4 = f & 15;
            float4 v = *(const float4*)(Kg + (size_t)(kt + n) * rs + c4 * 4);
            uint4 t = make_uint4(f2tf32(v.x), f2tf32(v.y), f2tf32(v.z), f2tf32(v.w));
            *(uint4*)(Ks + n * AST + c4 * 4) = t;
        }
        // V tile transposed: Vt[d][kv], rounded (scalar stores).
#pragma unroll
        for (int it = 0; it < 32; it++) {
            int f = tid + it * 128;
            int kv = f >> 6, d = f & 63;
            float v = Vg[(size_t)(kt + kv) * rs + d];
            Vt[d * AST + kv] = __uint_as_float(f2tf32(v));
        }
        __syncthreads();

        // ---- S = Q @ K^T  (warp: 32 x 64) ----
        float s[2][8][4];
#pragma unroll
        for (int mi = 0; mi < 2; mi++)
#pragma unroll
            for (int ni = 0; ni < 8; ni++)
#pragma unroll
                for (int j = 0; j < 4; j++) s[mi][ni][j] = 0.f;

#pragma unroll
        for (int kk = 0; kk < 64; kk += 8) {
            uint32_t af[2][4], bf[8][2];
#pragma unroll
            for (int mi = 0; mi < 2; mi++) {
                int m = warp * 32 + mi * 16 + (a_tile & 1) * 8 + a_r;
                int k = kk + (a_tile >> 1) * 4;
                ldsm_x4(af[mi], qs_b + (m * AST + k) * 4);
            }
#pragma unroll
            for (int np = 0; np < 4; np++) {
                int n = np * 16 + (a_tile >> 1) * 8 + a_r;
                int k = kk + (a_tile & 1) * 4;
                uint32_t tmp[4];
                ldsm_x4(tmp, ks_b + (n * AST + k) * 4);
                bf[np * 2][0]     = tmp[0]; bf[np * 2][1]     = tmp[1];
                bf[np * 2 + 1][0] = tmp[2]; bf[np * 2 + 1][1] = tmp[3];
            }
#pragma unroll
            for (int mi = 0; mi < 2; mi++)
#pragma unroll
                for (int ni = 0; ni < 8; ni++)
                    mma_tf32(s[mi][ni], af[mi], bf[ni]);
        }

        // ---- online softmax (rows live in 4-lane groups) ----
#pragma unroll
        for (int mi = 0; mi < 2; mi++)
#pragma unroll
            for (int hh = 0; hh < 2; hh++) {
                float tmax = -1e30f;
#pragma unroll
                for (int ni = 0; ni < 8; ni++) {
                    tmax = fmaxf(tmax, s[mi][ni][hh * 2]);
                    tmax = fmaxf(tmax, s[mi][ni][hh * 2 + 1]);
                }
                tmax = fmaxf(tmax, __shfl_xor_sync(0xffffffffu, tmax, 1));
                tmax = fmaxf(tmax, __shfl_xor_sync(0xffffffffu, tmax, 2));
                float mold = m_st[mi][hh];
                float mnew = fmaxf(mold, tmax);
                float alpha = __expf(mold - mnew);
                float sum = 0.f;
#pragma unroll
                for (int ni = 0; ni < 8; ni++) {
                    float p0 = __expf(s[mi][ni][hh * 2]     - mnew);
                    float p1 = __expf(s[mi][ni][hh * 2 + 1] - mnew);
                    s[mi][ni][hh * 2] = p0; s[mi][ni][hh * 2 + 1] = p1;
                    sum += p0 + p1;
                }
                sum += __shfl_xor_sync(0xffffffffu, sum, 1);
                sum += __shfl_xor_sync(0xffffffffu, sum, 2);
                l_st[mi][hh] = l_st[mi][hh] * alpha + sum;
                m_st[mi][hh] = mnew;
#pragma unroll
                for (int ni = 0; ni < 8; ni++) {
                    o[mi][ni][hh * 2]     *= alpha;
                    o[mi][ni][hh * 2 + 1] *= alpha;
                }
            }

        // ---- store P (tf32 bits) ----
#pragma unroll
        for (int mi = 0; mi < 2; mi++) {
            int m0 = warp * 32 + mi * 16 + r;
#pragma unroll
            for (int ni = 0; ni < 8; ni++) {
                int col = ni * 8 + q * 2;
                uint2 p0 = make_uint2(f2tf32(s[mi][ni][0]), f2tf32(s[mi][ni][1]));
                uint2 p1 = make_uint2(f2tf32(s[mi][ni][2]), f2tf32(s[mi][ni][3]));
                *(uint2*)(Ps + m0 * AST + col)       = p0;
                *(uint2*)(Ps + (m0 + 8) * AST + col) = p1;
            }
        }
        __syncthreads();

        // ---- O += P @ V  (A from Ps, B from Vt) ----
#pragma unroll
        for (int kk = 0; kk < 64; kk += 8) {
            uint32_t af[2][4], bf[8][2];
#pragma unroll
            for (int mi = 0; mi < 2; mi++) {
                int m = warp * 32 + mi * 16 + (a_tile & 1) * 8 + a_r;
                int k = kk + (a_tile >> 1) * 4;
                ldsm_x4(af[mi], ps_b + (m * AST + k) * 4);
            }
#pragma unroll
            for (int np = 0; np < 4; np++) {
                int n = np * 16 + (a_tile >> 1) * 8 + a_r;
                int k = kk + (a_tile & 1) * 4;
                uint32_t tmp[4];
                ldsm_x4(tmp, vt_b + (n * AST + k) * 4);
                bf[np * 2][0]     = tmp[0]; bf[np * 2][1]     = tmp[1];
                bf[np * 2 + 1][0] = tmp[2]; bf[np * 2 + 1][1] = tmp[3];
            }
#pragma unroll
            for (int mi = 0; mi < 2; mi++)
#pragma unroll
                for (int ni = 0; ni < 8; ni++)
                    mma_tf32(o[mi][ni], af[mi], bf[ni]);
        }
        __syncthreads();
    }

    // Epilogue: O / l, round to tf32 bits (feeds GEMM2), write out.
    const size_t orow = (size_t)b * SEQ + q0;
#pragma unroll
    for (int mi = 0; mi < 2; mi++) {
        float inv0 = 1.0f / l_st[mi][0];
        float inv1 = 1.0f / l_st[mi][1];
        int m0 = warp * 32 + mi * 16 + r;
#pragma unroll
        for (int ni = 0; ni < 8; ni++) {
            int col = h * HD + ni * 8 + q * 2;
            uint2 v0 = make_uint2(f2tf32(o[mi][ni][0] * inv0), f2tf32(o[mi][ni][1] * inv0));
            uint2 v1 = make_uint2(f2tf32(o[mi][ni][2] * inv1), f2tf32(o[mi][ni][3] * inv1));
            *(uint2*)(out + (orow + m0) * EMB + col)       = v0;
            *(uint2*)(out + (orow + m0 + 8) * EMB + col)   = v1;
        }
    }
}

// ===========================================================================
extern "C" void kernel_launch(void* const* d_in, const int* in_sizes, int n_in,
                              void* d_out, int out_size)
{
    const float* x     = (const float*)d_in[0];
    const float* w_in  = (const float*)d_in[1];
    const float* b_in  = (const float*)d_in[2];
    const float* w_out = (const float*)d_in[3];
    const float* b_out = (const float*)d_in[4];
    float* out = (float*)d_out;

    static float* x_buf    = nullptr;
    static float* qkv_buf  = nullptr;
    static float* attn_buf = nullptr;
    static float* w_inT    = nullptr;
    static float* w_outT   = nullptr;
    static bool   init     = false;
    if (!init) {
        cudaGetSymbolAddress((void**)&x_buf,    g_x);
        cudaGetSymbolAddress((void**)&qkv_buf,  g_qkv);
        cudaGetSymbolAddress((void**)&attn_buf, g_attn);
        cudaGetSymbolAddress((void**)&w_inT,    g_w_inT);
        cudaGetSymbolAddress((void**)&w_outT,   g_w_outT);
        cudaFuncSetAttribute(mha_mma_kernel,
                             cudaFuncAttributeMaxDynamicSharedMemorySize,
                             ATTN_SMEM_BYTES);
        cudaFuncSetAttribute(gemm_mma,
                             cudaFuncAttributeMaxDynamicSharedMemorySize,
                             65536);
        init = true;
    }

    // 0) Pre-round x; transpose+round weights to K-major tf32 bits.
    round_tf32_kernel<<<NTOK * EMB / 1024, 256>>>(x, x_buf);
    transpose_round_kernel<<<dim3(3 * EMB / 32, EMB / 32), dim3(32, 8)>>>(w_in,  w_inT,  EMB, 3 * EMB);
    transpose_round_kernel<<<dim3(EMB / 32,     EMB / 32), dim3(32, 8)>>>(w_out, w_outT, EMB, EMB);

    // 1) QKV projection: [4096,1024] @ [1024,3072] + b_in   (tf32 mma, cp.async)
    gemm_mma<<<dim3(3 * EMB / 128, NTOK / 128), 256, 65536>>>(
        x_buf, w_inT, b_in, qkv_buf, NTOK, 3 * EMB, EMB);

    // 2) Attention per (batch, head), 128-query tiles (tf32 mma flash)
    mha_mma_kernel<<<dim3(SEQ / 128, BATCH * NH), 128, ATTN_SMEM_BYTES>>>(
        qkv_buf, attn_buf);

    // 3) Output projection: [4096,1024] @ [1024,1024] + b_out  (tf32 mma, cp.async)
    gemm_mma<<<dim3(EMB / 128, NTOK / 128), 256, 65536>>>(
        attn_buf, w_outT, b_out, out, NTOK, EMB, EMB);
}